// round 1
// baseline (speedup 1.0000x reference)
#include <cuda_runtime.h>
#include <math.h>

#define B_   4096
#define IN_  1024
#define H_   1024
#define F_   128
#define T_   3
#define G_   4096      // 4*H
#define LN_EPS 1e-5f

// ---------------- scratch (no allocations allowed) ----------------
__device__ float g_xs[B_ * F_];                 // (input_ @ w_ih_c^T) * scale_i
__device__ float g_hs[B_ * F_];                 // (hx @ w_hh_c^T) * scale_h
__device__ float g_ig[(size_t)B_ * G_];         // igates
__device__ float g_hg[(size_t)B_ * G_];         // hgates

// =====================================================================
// Stage 1: out[b,f] = (sum_k x[b,k]*wc[f,k]) * (sum_t theta[b,t]*wb[f,t])
//          theta[b,t] = sum_t' topic[b,t']*thw[t,t'] + thb[t]
// Tile: 64 rows x 128 cols (all of F), BK=16, 256 threads, TM=4 TN=8.
// gridDim = (B/64, 2): y==0 -> input path, y==1 -> h path. K = 1024 both.
// =====================================================================
__global__ __launch_bounds__(256) void stage1_kernel(
    const float* __restrict__ x_i,  const float* __restrict__ wc_i,
    const float* __restrict__ wb_i, const float* __restrict__ thw_i,
    const float* __restrict__ thb_i,
    const float* __restrict__ x_h,  const float* __restrict__ wc_h,
    const float* __restrict__ wb_h, const float* __restrict__ thw_h,
    const float* __restrict__ thb_h,
    const float* __restrict__ topic)
{
    const bool hp = (blockIdx.y == 1);
    const float* __restrict__ x   = hp ? x_h   : x_i;
    const float* __restrict__ wc  = hp ? wc_h  : wc_i;
    const float* __restrict__ wb  = hp ? wb_h  : wb_i;
    const float* __restrict__ thw = hp ? thw_h : thw_i;
    const float* __restrict__ thb = hp ? thb_h : thb_i;
    float* __restrict__ outp      = hp ? g_hs  : g_xs;

    __shared__ float sA[16][68];    // [k][m]
    __shared__ float sB[16][132];   // [k][n]
    __shared__ float sTheta[64][4]; // per-row theta (3 used)

    const int tid  = threadIdx.x;
    const int row0 = blockIdx.x * 64;

    if (tid < 192) {
        int r = tid / 3, t = tid - r * 3;
        const float* tp = topic + (size_t)(row0 + r) * T_;
        sTheta[r][t] = thb[t] + tp[0]*thw[t*T_+0] + tp[1]*thw[t*T_+1] + tp[2]*thw[t*T_+2];
    }

    const int tx = tid & 15;   // -> 8 cols
    const int ty = tid >> 4;   // -> 4 rows
    const int m0 = ty * 4;
    const int n0 = tx * 8;

    float acc[4][8];
    #pragma unroll
    for (int m = 0; m < 4; m++)
        #pragma unroll
        for (int n = 0; n < 8; n++) acc[m][n] = 0.f;

    for (int k0 = 0; k0 < 1024; k0 += 16) {
        #pragma unroll
        for (int i = 0; i < 4; i++) {           // A: 64x16
            int idx = tid + i * 256;
            int r = idx >> 4, k = idx & 15;
            sA[k][r] = x[(size_t)(row0 + r) * 1024 + k0 + k];
        }
        #pragma unroll
        for (int i = 0; i < 8; i++) {           // B: 128x16 (wc is [F][K])
            int idx = tid + i * 256;
            int n = idx >> 4, k = idx & 15;
            sB[k][n] = wc[(size_t)n * 1024 + k0 + k];
        }
        __syncthreads();
        #pragma unroll
        for (int k = 0; k < 16; k++) {
            float4 a0 = *reinterpret_cast<const float4*>(&sA[k][m0]);
            float4 b0 = *reinterpret_cast<const float4*>(&sB[k][n0]);
            float4 b1 = *reinterpret_cast<const float4*>(&sB[k][n0 + 4]);
            float a[4] = {a0.x, a0.y, a0.z, a0.w};
            float b[8] = {b0.x, b0.y, b0.z, b0.w, b1.x, b1.y, b1.z, b1.w};
            #pragma unroll
            for (int m = 0; m < 4; m++)
                #pragma unroll
                for (int n = 0; n < 8; n++) acc[m][n] += a[m] * b[n];
        }
        __syncthreads();
    }

    // epilogue: multiply by scale(b,f) = sum_t theta[b,t]*wb[f,t]
    #pragma unroll
    for (int n = 0; n < 8; n++) {
        int f = n0 + n;
        float w0 = wb[f*T_+0], w1 = wb[f*T_+1], w2 = wb[f*T_+2];
        #pragma unroll
        for (int m = 0; m < 4; m++) {
            int r = m0 + m;
            float sc = sTheta[r][0]*w0 + sTheta[r][1]*w1 + sTheta[r][2]*w2;
            outp[(size_t)(row0 + r) * F_ + f] = acc[m][n] * sc;
        }
    }
}

// =====================================================================
// Stage 2: gates[b,n] = sum_f A[b,f] * W[n,f]   (K = F = 128)
// Tile 128x128, BK=16, 256 threads, TM=TN=8.
// gridDim = (G/128, B/128, 2); z==0 -> (g_xs,w_ih_a,g_ig), z==1 -> h path.
// =====================================================================
__global__ __launch_bounds__(256) void stage2_kernel(
    const float* __restrict__ wa_i, const float* __restrict__ wa_h)
{
    const bool hp = (blockIdx.z == 1);
    const float* __restrict__ A = hp ? g_hs : g_xs;
    const float* __restrict__ W = hp ? wa_h : wa_i;
    float* __restrict__ O       = hp ? g_hg : g_ig;

    const int col0 = blockIdx.x * 128;
    const int row0 = blockIdx.y * 128;

    __shared__ float sA[16][132];
    __shared__ float sB[16][132];

    const int tid = threadIdx.x;
    const int tx = tid & 15;
    const int ty = tid >> 4;
    const int m0 = ty * 8;
    const int n0 = tx * 8;

    float acc[8][8];
    #pragma unroll
    for (int m = 0; m < 8; m++)
        #pragma unroll
        for (int n = 0; n < 8; n++) acc[m][n] = 0.f;

    for (int k0 = 0; k0 < 128; k0 += 16) {
        #pragma unroll
        for (int i = 0; i < 8; i++) {
            int idx = tid + i * 256;
            int r = idx >> 4, k = idx & 15;
            sA[k][r] = A[(size_t)(row0 + r) * F_ + k0 + k];
        }
        #pragma unroll
        for (int i = 0; i < 8; i++) {
            int idx = tid + i * 256;
            int n = idx >> 4, k = idx & 15;
            sB[k][n] = W[(size_t)(col0 + n) * F_ + k0 + k];
        }
        __syncthreads();
        #pragma unroll
        for (int k = 0; k < 16; k++) {
            float4 a0 = *reinterpret_cast<const float4*>(&sA[k][m0]);
            float4 a1 = *reinterpret_cast<const float4*>(&sA[k][m0 + 4]);
            float4 b0 = *reinterpret_cast<const float4*>(&sB[k][n0]);
            float4 b1 = *reinterpret_cast<const float4*>(&sB[k][n0 + 4]);
            float a[8] = {a0.x, a0.y, a0.z, a0.w, a1.x, a1.y, a1.z, a1.w};
            float b[8] = {b0.x, b0.y, b0.z, b0.w, b1.x, b1.y, b1.z, b1.w};
            #pragma unroll
            for (int m = 0; m < 8; m++)
                #pragma unroll
                for (int n = 0; n < 8; n++) acc[m][n] += a[m] * b[n];
        }
        __syncthreads();
    }

    #pragma unroll
    for (int m = 0; m < 8; m++) {
        float4* dst = reinterpret_cast<float4*>(
            &O[(size_t)(row0 + m0 + m) * G_ + col0 + n0]);
        dst[0] = make_float4(acc[m][0], acc[m][1], acc[m][2], acc[m][3]);
        dst[1] = make_float4(acc[m][4], acc[m][5], acc[m][6], acc[m][7]);
    }
}

// =====================================================================
// Stage 3: per-row LN(igates)+LN(hgates), gate nonlinearities, cell update,
// LN over cell, outputs hy (first B*H) then cy (next B*H).
// One CTA (256 threads) per batch row.
// =====================================================================
__device__ __forceinline__ float sigm(float x) { return 1.f / (1.f + expf(-x)); }

__device__ __forceinline__ float2 block_reduce2(float s, float q, float* red)
{
    __syncthreads();  // protect red reuse across calls
    #pragma unroll
    for (int o = 16; o > 0; o >>= 1) {
        s += __shfl_xor_sync(0xffffffffu, s, o);
        q += __shfl_xor_sync(0xffffffffu, q, o);
    }
    int w = threadIdx.x >> 5, l = threadIdx.x & 31;
    if (l == 0) { red[w] = s; red[8 + w] = q; }
    __syncthreads();
    if (w == 0) {
        s = (l < 8) ? red[l] : 0.f;
        q = (l < 8) ? red[8 + l] : 0.f;
        #pragma unroll
        for (int o = 4; o > 0; o >>= 1) {
            s += __shfl_xor_sync(0xffffffffu, s, o);
            q += __shfl_xor_sync(0xffffffffu, q, o);
        }
        if (l == 0) { red[0] = s; red[1] = q; }
    }
    __syncthreads();
    return make_float2(red[0], red[1]);
}

__global__ __launch_bounds__(256) void stage3_kernel(
    const float* __restrict__ cx,
    const float* __restrict__ lniw, const float* __restrict__ lnib,
    const float* __restrict__ lnhw, const float* __restrict__ lnhb,
    const float* __restrict__ lncw, const float* __restrict__ lncb,
    float* __restrict__ out)
{
    __shared__ float s_ig[G_];
    __shared__ float s_hg[G_];
    __shared__ float red[16];

    const int r   = blockIdx.x;
    const int tid = threadIdx.x;
    const float* __restrict__ igr = g_ig + (size_t)r * G_;
    const float* __restrict__ hgr = g_hg + (size_t)r * G_;

    float s = 0.f, q = 0.f;
    #pragma unroll
    for (int i = 0; i < 16; i++) {
        int n = tid + i * 256;
        float v = igr[n];
        s_ig[n] = v; s += v; q += v * v;
    }
    float2 ri = block_reduce2(s, q, red);
    float mu_i = ri.x * (1.f / G_);
    float rstd_i = rsqrtf(ri.y * (1.f / G_) - mu_i * mu_i + LN_EPS);

    s = 0.f; q = 0.f;
    #pragma unroll
    for (int i = 0; i < 16; i++) {
        int n = tid + i * 256;
        float v = hgr[n];
        s_hg[n] = v; s += v; q += v * v;
    }
    float2 rh = block_reduce2(s, q, red);
    float mu_h = rh.x * (1.f / G_);
    float rstd_h = rsqrtf(rh.y * (1.f / G_) - mu_h * mu_h + LN_EPS);

    // gates + cell update (each thread owns 4 hidden units; keep in regs)
    float cc[4], oo[4];
    float cs = 0.f, cq = 0.f;
    #pragma unroll
    for (int i = 0; i < 4; i++) {
        int j = tid + i * 256;
        #define GVAL(n) ((s_ig[(n)] - mu_i) * rstd_i * lniw[(n)] + lnib[(n)] + \
                         (s_hg[(n)] - mu_h) * rstd_h * lnhw[(n)] + lnhb[(n)])
        float gi = sigm(GVAL(j));
        float gf = sigm(GVAL(j + H_));
        float gg = tanhf(GVAL(j + 2 * H_));
        float go = sigm(GVAL(j + 3 * H_));
        #undef GVAL
        float c = gf * cx[(size_t)r * H_ + j] + gi * gg;
        cc[i] = c; oo[i] = go;
        cs += c; cq += c * c;
    }
    float2 rc = block_reduce2(cs, cq, red);
    float mu_c = rc.x * (1.f / H_);
    float rstd_c = rsqrtf(rc.y * (1.f / H_) - mu_c * mu_c + LN_EPS);

    #pragma unroll
    for (int i = 0; i < 4; i++) {
        int j = tid + i * 256;
        float cy = (cc[i] - mu_c) * rstd_c * lncw[j] + lncb[j];
        float hy = oo[i] * tanhf(cy);
        out[(size_t)r * H_ + j] = hy;
        out[(size_t)B_ * H_ + (size_t)r * H_ + j] = cy;
    }
}

// =====================================================================
extern "C" void kernel_launch(void* const* d_in, const int* in_sizes, int n_in,
                              void* d_out, int out_size)
{
    const float* input_ = (const float*)d_in[0];
    const float* hx     = (const float*)d_in[1];
    const float* cx     = (const float*)d_in[2];
    const float* topic  = (const float*)d_in[3];
    const float* w_ih_a = (const float*)d_in[4];
    const float* w_ih_b = (const float*)d_in[5];
    const float* w_ih_c = (const float*)d_in[6];
    const float* w_hh_a = (const float*)d_in[7];
    const float* w_hh_b = (const float*)d_in[8];
    const float* w_hh_c = (const float*)d_in[9];
    const float* th_ih_w = (const float*)d_in[10];
    const float* th_ih_b = (const float*)d_in[11];
    const float* th_hh_w = (const float*)d_in[12];
    const float* th_hh_b = (const float*)d_in[13];
    const float* ln_i_w  = (const float*)d_in[14];
    const float* ln_i_b  = (const float*)d_in[15];
    const float* ln_h_w  = (const float*)d_in[16];
    const float* ln_h_b  = (const float*)d_in[17];
    const float* ln_c_w  = (const float*)d_in[18];
    const float* ln_c_b  = (const float*)d_in[19];

    stage1_kernel<<<dim3(B_ / 64, 2), 256>>>(
        input_, w_ih_c, w_ih_b, th_ih_w, th_ih_b,
        hx,     w_hh_c, w_hh_b, th_hh_w, th_hh_b,
        topic);

    stage2_kernel<<<dim3(G_ / 128, B_ / 128, 2), 256>>>(w_ih_a, w_hh_a);

    stage3_kernel<<<B_, 256>>>(cx, ln_i_w, ln_i_b, ln_h_w, ln_h_b,
                               ln_c_w, ln_c_b, (float*)d_out);
}

// round 5
// speedup vs baseline: 1.3387x; 1.3387x over previous
#include <cuda_runtime.h>
#include <cuda_bf16.h>
#include <math.h>
#include <stdint.h>

#define B_   4096
#define IN_  1024
#define H_   1024
#define F_   128
#define T_   3
#define G_   4096      // 4*H
#define K2_  256       // stored split-bf16 K (hi|lo)
#define LN_EPS 1e-5f

// ---------------- scratch (no allocations allowed) ----------------
__device__ __align__(16) __nv_bfloat16 g_a2[2][(size_t)B_ * K2_]; // stage1 out (hi|lo)
__device__ __align__(16) __nv_bfloat16 g_w2[2][(size_t)G_ * K2_]; // w_*_a  (hi|lo)
__device__ float g_ig[(size_t)B_ * G_];
__device__ float g_hg[(size_t)B_ * G_];

__device__ __forceinline__ uint32_t smem_u32(const void* p) {
    uint32_t a;
    asm("{ .reg .u64 t; cvta.to.shared.u64 t, %1; cvt.u32.u64 %0, t; }"
        : "=r"(a) : "l"(p));
    return a;
}

// =====================================================================
// Weight convert: fp32 [4096,128] -> bf16 hi|lo [4096,256]
// =====================================================================
__global__ __launch_bounds__(128) void convert_w_kernel(
    const float* __restrict__ wi, const float* __restrict__ wh)
{
    const int n = blockIdx.x, path = blockIdx.y, f = threadIdx.x;
    const float* w = path ? wh : wi;
    float v = w[(size_t)n * F_ + f];
    __nv_bfloat16 hi = __float2bfloat16(v);
    float lo = v - __bfloat162float(hi);
    g_w2[path][(size_t)n * K2_ + f]        = hi;
    g_w2[path][(size_t)n * K2_ + 128 + f]  = __float2bfloat16(lo);
}

// =====================================================================
// Stage 1: out[b,f] = (sum_k x[b,k]*wc[f,k]) * (sum_t theta[b,t]*wb[f,t])
// Tile 32 rows x 128 cols, BK=16, 256 threads, TM=2 TN=8. grid (B/32, 2).
// Epilogue writes bf16 hi|lo split into g_a2.
// =====================================================================
__global__ __launch_bounds__(256) void stage1_kernel(
    const float* __restrict__ x_i,  const float* __restrict__ wc_i,
    const float* __restrict__ wb_i, const float* __restrict__ thw_i,
    const float* __restrict__ thb_i,
    const float* __restrict__ x_h,  const float* __restrict__ wc_h,
    const float* __restrict__ wb_h, const float* __restrict__ thw_h,
    const float* __restrict__ thb_h,
    const float* __restrict__ topic)
{
    const int hp = blockIdx.y;
    const float* __restrict__ x   = hp ? x_h   : x_i;
    const float* __restrict__ wc  = hp ? wc_h  : wc_i;
    const float* __restrict__ wb  = hp ? wb_h  : wb_i;
    const float* __restrict__ thw = hp ? thw_h : thw_i;
    const float* __restrict__ thb = hp ? thb_h : thb_i;
    __nv_bfloat16* __restrict__ outp = g_a2[hp];

    __shared__ float sA[16][36];
    __shared__ float sB[16][132];
    __shared__ float sTheta[32][4];

    const int tid  = threadIdx.x;
    const int row0 = blockIdx.x * 32;

    if (tid < 96) {
        int r = tid / 3, t = tid - r * 3;
        const float* tp = topic + (size_t)(row0 + r) * T_;
        sTheta[r][t] = thb[t] + tp[0]*thw[t*T_+0] + tp[1]*thw[t*T_+1] + tp[2]*thw[t*T_+2];
    }

    const int tx = tid & 15;
    const int ty = tid >> 4;
    const int m0 = ty * 2;
    const int n0 = tx * 8;

    float acc[2][8];
    #pragma unroll
    for (int m = 0; m < 2; m++)
        #pragma unroll
        for (int n = 0; n < 8; n++) acc[m][n] = 0.f;

    for (int k0 = 0; k0 < 1024; k0 += 16) {
        #pragma unroll
        for (int i = 0; i < 2; i++) {           // A: 32x16
            int idx = tid + i * 256;
            int r = idx >> 4, k = idx & 15;
            sA[k][r] = x[(size_t)(row0 + r) * 1024 + k0 + k];
        }
        #pragma unroll
        for (int i = 0; i < 8; i++) {           // B: 128x16 (wc is [F][K])
            int idx = tid + i * 256;
            int n = idx >> 4, k = idx & 15;
            sB[k][n] = wc[(size_t)n * 1024 + k0 + k];
        }
        __syncthreads();
        #pragma unroll
        for (int k = 0; k < 16; k++) {
            float2 a0 = *reinterpret_cast<const float2*>(&sA[k][m0]);
            float4 b0 = *reinterpret_cast<const float4*>(&sB[k][n0]);
            float4 b1 = *reinterpret_cast<const float4*>(&sB[k][n0 + 4]);
            float a[2] = {a0.x, a0.y};
            float b[8] = {b0.x, b0.y, b0.z, b0.w, b1.x, b1.y, b1.z, b1.w};
            #pragma unroll
            for (int m = 0; m < 2; m++)
                #pragma unroll
                for (int n = 0; n < 8; n++) acc[m][n] += a[m] * b[n];
        }
        __syncthreads();
    }

    #pragma unroll
    for (int n = 0; n < 8; n++) {
        int f = n0 + n;
        float w0 = wb[f*T_+0], w1 = wb[f*T_+1], w2 = wb[f*T_+2];
        #pragma unroll
        for (int m = 0; m < 2; m++) {
            int r = m0 + m;
            float sc = sTheta[r][0]*w0 + sTheta[r][1]*w1 + sTheta[r][2]*w2;
            float v = acc[m][n] * sc;
            __nv_bfloat16 hi = __float2bfloat16(v);
            float lo = v - __bfloat162float(hi);
            outp[(size_t)(row0 + r) * K2_ + f]       = hi;
            outp[(size_t)(row0 + r) * K2_ + 128 + f] = __float2bfloat16(lo);
        }
    }
}

// =====================================================================
// Stage 2: bf16 mma.sync GEMM with error-compensated K=384:
//   A smem row: [hi_a | lo_a | hi_a], W smem row: [hi_w | hi_w | lo_w]
//   sum = hi*hi + lo_a*hi_w + hi_a*lo_w  (err ~ 1e-5 rel)
// CTA tile M=128 x N=128. 8 warps (2x4), each 64x32.
// grid = (G/128, B/128, 2), 256 threads.
// =====================================================================
#define S2_LD   392                          // padded row (bf16 elems), 384+8
#define S2_TOT  (2 * 128 * S2_LD * 2)        // 200704 bytes

__global__ __launch_bounds__(256) void stage2_mma_kernel()
{
    extern __shared__ __nv_bfloat16 smem[];
    __nv_bfloat16* As = smem;                 // [128][392]
    __nv_bfloat16* Bs = smem + 128 * S2_LD;   // [128][392]

    const int tid  = threadIdx.x;
    const int lane = tid & 31;
    const int wid  = tid >> 5;
    const int path = blockIdx.z;
    const int row0 = blockIdx.y * 128;
    const int col0 = blockIdx.x * 128;

    const __nv_bfloat16* __restrict__ A = g_a2[path];
    const __nv_bfloat16* __restrict__ W = g_w2[path];
    float* __restrict__ O = path ? g_hg : g_ig;

    // ---- global -> smem with K replication (48 16B-chunks per row) ----
    // A: chunk cc -> src (cc < 32 ? cc : cc - 32)   [hi | lo | hi]
    // W: chunk cc -> src (cc < 16 ? cc : cc - 16)   [hi | hi | lo]
    #pragma unroll
    for (int id = 0; id < 24; id++) {
        int idx = tid + id * 256;             // 0 .. 6143
        int r  = idx / 48;
        int cc = idx - r * 48;
        int ca = (cc < 32) ? cc : cc - 32;
        int cw = (cc < 16) ? cc : cc - 16;
        *reinterpret_cast<uint4*>(&As[r * S2_LD + cc * 8]) =
            *reinterpret_cast<const uint4*>(A + (size_t)(row0 + r) * K2_ + ca * 8);
        *reinterpret_cast<uint4*>(&Bs[r * S2_LD + cc * 8]) =
            *reinterpret_cast<const uint4*>(W + (size_t)(col0 + r) * K2_ + cw * 8);
    }
    __syncthreads();

    const int wm = (wid & 1) * 64;            // warp m-offset in tile
    const int wn = (wid >> 1) * 32;           // warp n-offset in tile

    const uint32_t as_base = smem_u32(As);
    const uint32_t bs_base = smem_u32(Bs);

    float acc[4][4][4];
    #pragma unroll
    for (int mt = 0; mt < 4; mt++)
        #pragma unroll
        for (int nt = 0; nt < 4; nt++)
            #pragma unroll
            for (int j = 0; j < 4; j++) acc[mt][nt][j] = 0.f;

    const int lr  = lane & 7;
    const int seg = lane >> 3;                // 0..3  (A x4)
    const int l16 = lane & 15;                // (B x2)

    #pragma unroll
    for (int ks = 0; ks < 24; ks++) {
        const int k0 = ks * 16;

        uint32_t a[4][4];
        #pragma unroll
        for (int mt = 0; mt < 4; mt++) {
            int arow = wm + mt * 16 + lr + ((seg & 1) << 3);
            int acol = k0 + ((seg >> 1) << 3);
            uint32_t addr = as_base + (uint32_t)(arow * S2_LD + acol) * 2;
            asm volatile("ldmatrix.sync.aligned.m8n8.x4.shared.b16 {%0,%1,%2,%3}, [%4];"
                         : "=r"(a[mt][0]), "=r"(a[mt][1]), "=r"(a[mt][2]), "=r"(a[mt][3])
                         : "r"(addr));
        }
        uint32_t b[4][2];
        #pragma unroll
        for (int nt = 0; nt < 4; nt++) {
            int brow = wn + nt * 8 + (l16 & 7);
            int bcol = k0 + ((l16 >> 3) << 3);
            uint32_t addr = bs_base + (uint32_t)(brow * S2_LD + bcol) * 2;
            asm volatile("ldmatrix.sync.aligned.m8n8.x2.shared.b16 {%0,%1}, [%2];"
                         : "=r"(b[nt][0]), "=r"(b[nt][1])
                         : "r"(addr));
        }
        #pragma unroll
        for (int mt = 0; mt < 4; mt++)
            #pragma unroll
            for (int nt = 0; nt < 4; nt++) {
                asm volatile(
                    "mma.sync.aligned.m16n8k16.row.col.f32.bf16.bf16.f32 "
                    "{%0,%1,%2,%3}, {%4,%5,%6,%7}, {%8,%9}, {%0,%1,%2,%3};"
                    : "+f"(acc[mt][nt][0]), "+f"(acc[mt][nt][1]),
                      "+f"(acc[mt][nt][2]), "+f"(acc[mt][nt][3])
                    : "r"(a[mt][0]), "r"(a[mt][1]), "r"(a[mt][2]), "r"(a[mt][3]),
                      "r"(b[nt][0]), "r"(b[nt][1]));
            }
    }

    // ---- epilogue ----
    const int em = lane >> 2;
    const int en = (lane & 3) * 2;
    #pragma unroll
    for (int mt = 0; mt < 4; mt++) {
        #pragma unroll
        for (int nt = 0; nt < 4; nt++) {
            int m = row0 + wm + mt * 16 + em;
            int n = col0 + wn + nt * 8 + en;
            *reinterpret_cast<float2*>(&O[(size_t)m * G_ + n]) =
                make_float2(acc[mt][nt][0], acc[mt][nt][1]);
            *reinterpret_cast<float2*>(&O[(size_t)(m + 8) * G_ + n]) =
                make_float2(acc[mt][nt][2], acc[mt][nt][3]);
        }
    }
}

// =====================================================================
// Stage 3: per-row LN(igates)+LN(hgates), gates, cell update, LN(cell).
// =====================================================================
__device__ __forceinline__ float sigm(float x) { return 1.f / (1.f + expf(-x)); }

__device__ __forceinline__ float2 block_reduce2(float s, float q, float* red)
{
    __syncthreads();
    #pragma unroll
    for (int o = 16; o > 0; o >>= 1) {
        s += __shfl_xor_sync(0xffffffffu, s, o);
        q += __shfl_xor_sync(0xffffffffu, q, o);
    }
    int w = threadIdx.x >> 5, l = threadIdx.x & 31;
    if (l == 0) { red[w] = s; red[8 + w] = q; }
    __syncthreads();
    if (w == 0) {
        s = (l < 8) ? red[l] : 0.f;
        q = (l < 8) ? red[8 + l] : 0.f;
        #pragma unroll
        for (int o = 4; o > 0; o >>= 1) {
            s += __shfl_xor_sync(0xffffffffu, s, o);
            q += __shfl_xor_sync(0xffffffffu, q, o);
        }
        if (l == 0) { red[0] = s; red[1] = q; }
    }
    __syncthreads();
    return make_float2(red[0], red[1]);
}

__global__ __launch_bounds__(256) void stage3_kernel(
    const float* __restrict__ cx,
    const float* __restrict__ lniw, const float* __restrict__ lnib,
    const float* __restrict__ lnhw, const float* __restrict__ lnhb,
    const float* __restrict__ lncw, const float* __restrict__ lncb,
    float* __restrict__ out)
{
    __shared__ float s_ig[G_];
    __shared__ float s_hg[G_];
    __shared__ float red[16];

    const int r   = blockIdx.x;
    const int tid = threadIdx.x;
    const float* __restrict__ igr = g_ig + (size_t)r * G_;
    const float* __restrict__ hgr = g_hg + (size_t)r * G_;

    float s = 0.f, q = 0.f;
    #pragma unroll
    for (int i = 0; i < 16; i++) {
        int n = tid + i * 256;
        float v = igr[n];
        s_ig[n] = v; s += v; q += v * v;
    }
    float2 ri = block_reduce2(s, q, red);
    float mu_i = ri.x * (1.f / G_);
    float rstd_i = rsqrtf(ri.y * (1.f / G_) - mu_i * mu_i + LN_EPS);

    s = 0.f; q = 0.f;
    #pragma unroll
    for (int i = 0; i < 16; i++) {
        int n = tid + i * 256;
        float v = hgr[n];
        s_hg[n] = v; s += v; q += v * v;
    }
    float2 rh = block_reduce2(s, q, red);
    float mu_h = rh.x * (1.f / G_);
    float rstd_h = rsqrtf(rh.y * (1.f / G_) - mu_h * mu_h + LN_EPS);

    float cc[4], oo[4];
    float cs = 0.f, cq = 0.f;
    #pragma unroll
    for (int i = 0; i < 4; i++) {
        int j = tid + i * 256;
        #define GVAL(n) ((s_ig[(n)] - mu_i) * rstd_i * lniw[(n)] + lnib[(n)] + \
                         (s_hg[(n)] - mu_h) * rstd_h * lnhw[(n)] + lnhb[(n)])
        float gi = sigm(GVAL(j));
        float gf = sigm(GVAL(j + H_));
        float gg = tanhf(GVAL(j + 2 * H_));
        float go = sigm(GVAL(j + 3 * H_));
        #undef GVAL
        float c = gf * cx[(size_t)r * H_ + j] + gi * gg;
        cc[i] = c; oo[i] = go;
        cs += c; cq += c * c;
    }
    float2 rc = block_reduce2(cs, cq, red);
    float mu_c = rc.x * (1.f / H_);
    float rstd_c = rsqrtf(rc.y * (1.f / H_) - mu_c * mu_c + LN_EPS);

    #pragma unroll
    for (int i = 0; i < 4; i++) {
        int j = tid + i * 256;
        float cy = (cc[i] - mu_c) * rstd_c * lncw[j] + lncb[j];
        float hy = oo[i] * tanhf(cy);
        out[(size_t)r * H_ + j] = hy;
        out[(size_t)B_ * H_ + (size_t)r * H_ + j] = cy;
    }
}

// =====================================================================
extern "C" void kernel_launch(void* const* d_in, const int* in_sizes, int n_in,
                              void* d_out, int out_size)
{
    const float* input_ = (const float*)d_in[0];
    const float* hx     = (const float*)d_in[1];
    const float* cx     = (const float*)d_in[2];
    const float* topic  = (const float*)d_in[3];
    const float* w_ih_a = (const float*)d_in[4];
    const float* w_ih_b = (const float*)d_in[5];
    const float* w_ih_c = (const float*)d_in[6];
    const float* w_hh_a = (const float*)d_in[7];
    const float* w_hh_b = (const float*)d_in[8];
    const float* w_hh_c = (const float*)d_in[9];
    const float* th_ih_w = (const float*)d_in[10];
    const float* th_ih_b = (const float*)d_in[11];
    const float* th_hh_w = (const float*)d_in[12];
    const float* th_hh_b = (const float*)d_in[13];
    const float* ln_i_w  = (const float*)d_in[14];
    const float* ln_i_b  = (const float*)d_in[15];
    const float* ln_h_w  = (const float*)d_in[16];
    const float* ln_h_b  = (const float*)d_in[17];
    const float* ln_c_w  = (const float*)d_in[18];
    const float* ln_c_b  = (const float*)d_in[19];

    cudaFuncSetAttribute(stage2_mma_kernel,
                         cudaFuncAttributeMaxDynamicSharedMemorySize, S2_TOT);

    convert_w_kernel<<<dim3(G_, 2), 128>>>(w_ih_a, w_hh_a);

    stage1_kernel<<<dim3(B_ / 32, 2), 256>>>(
        input_, w_ih_c, w_ih_b, th_ih_w, th_ih_b,
        hx,     w_hh_c, w_hh_b, th_hh_w, th_hh_b,
        topic);

    stage2_mma_kernel<<<dim3(G_ / 128, B_ / 128, 2), 256, S2_TOT>>>();

    stage3_kernel<<<B_, 256>>>(cx, ln_i_w, ln_i_b, ln_h_w, ln_h_b,
                               ln_c_w, ln_c_b, (float*)d_out);
}

// round 6
// speedup vs baseline: 2.0972x; 1.5666x over previous
#include <cuda_runtime.h>
#include <cuda_bf16.h>
#include <math.h>
#include <stdint.h>

#define B_   4096
#define IN_  1024
#define H_   1024
#define F_   128
#define T_   3
#define G_   4096      // 4*H
#define K2_  256       // stored split-bf16 K (hi|lo)
#define LN_EPS 1e-5f

// ---------------- scratch (no allocations allowed) ----------------
__device__ __align__(16) __nv_bfloat16 g_x2[2][2][(size_t)B_ * IN_];  // x/hx hi,lo planes
__device__ __align__(16) __nv_bfloat16 g_wc2[2][2][(size_t)F_ * IN_]; // wc hi,lo planes
__device__ __align__(16) __nv_bfloat16 g_a2[2][(size_t)B_ * K2_];     // stage1 out (hi|lo)
__device__ __align__(16) __nv_bfloat16 g_w2[2][(size_t)G_ * K2_];     // w_*_a  (hi|lo)
__device__ float g_ig[(size_t)B_ * G_];
__device__ float g_hg[(size_t)B_ * G_];

__device__ __forceinline__ uint32_t smem_u32(const void* p) {
    uint32_t a;
    asm("{ .reg .u64 t; cvta.to.shared.u64 t, %1; cvt.u32.u64 %0, t; }"
        : "=r"(a) : "l"(p));
    return a;
}
__device__ __forceinline__ void cp16(uint32_t dst, const void* src) {
    asm volatile("cp.async.cg.shared.global [%0], [%1], 16;"
                 :: "r"(dst), "l"(src));
}
#define CP_COMMIT()  asm volatile("cp.async.commit_group;")
#define CP_WAIT(n)   asm volatile("cp.async.wait_group %0;" :: "n"(n))

__device__ __forceinline__ float f4c(const float4& v, int c) {
    return reinterpret_cast<const float*>(&v)[c];
}

// =====================================================================
// convert_x: x / hx fp32 [4096,1024] -> bf16 hi,lo planes. grid (B_,2)x256
// =====================================================================
__global__ __launch_bounds__(256) void convert_x_kernel(
    const float* __restrict__ xi, const float* __restrict__ xh)
{
    const int path = blockIdx.y, row = blockIdx.x, tid = threadIdx.x;
    const float* x = path ? xh : xi;
    float4 v = reinterpret_cast<const float4*>(x + (size_t)row * IN_)[tid];
    __nv_bfloat16 hx_ = __float2bfloat16(v.x);
    __nv_bfloat16 hy_ = __float2bfloat16(v.y);
    __nv_bfloat16 hz_ = __float2bfloat16(v.z);
    __nv_bfloat16 hw_ = __float2bfloat16(v.w);
    __nv_bfloat162* hi = reinterpret_cast<__nv_bfloat162*>(
        g_x2[path][0] + (size_t)row * IN_);
    __nv_bfloat162* lo = reinterpret_cast<__nv_bfloat162*>(
        g_x2[path][1] + (size_t)row * IN_);
    hi[tid*2]   = __nv_bfloat162(hx_, hy_);
    hi[tid*2+1] = __nv_bfloat162(hz_, hw_);
    lo[tid*2]   = __nv_bfloat162(__float2bfloat16(v.x - __bfloat162float(hx_)),
                                 __float2bfloat16(v.y - __bfloat162float(hy_)));
    lo[tid*2+1] = __nv_bfloat162(__float2bfloat16(v.z - __bfloat162float(hz_)),
                                 __float2bfloat16(v.w - __bfloat162float(hw_)));
}

// =====================================================================
// convert_wc: wc fp32 [128,1024] -> bf16 hi,lo planes. grid (F_,2)x256
// =====================================================================
__global__ __launch_bounds__(256) void convert_wc_kernel(
    const float* __restrict__ wi, const float* __restrict__ wh)
{
    const int path = blockIdx.y, row = blockIdx.x, tid = threadIdx.x;
    const float* w = path ? wh : wi;
    float4 v = reinterpret_cast<const float4*>(w + (size_t)row * IN_)[tid];
    __nv_bfloat16 hx_ = __float2bfloat16(v.x);
    __nv_bfloat16 hy_ = __float2bfloat16(v.y);
    __nv_bfloat16 hz_ = __float2bfloat16(v.z);
    __nv_bfloat16 hw_ = __float2bfloat16(v.w);
    __nv_bfloat162* hi = reinterpret_cast<__nv_bfloat162*>(
        g_wc2[path][0] + (size_t)row * IN_);
    __nv_bfloat162* lo = reinterpret_cast<__nv_bfloat162*>(
        g_wc2[path][1] + (size_t)row * IN_);
    hi[tid*2]   = __nv_bfloat162(hx_, hy_);
    hi[tid*2+1] = __nv_bfloat162(hz_, hw_);
    lo[tid*2]   = __nv_bfloat162(__float2bfloat16(v.x - __bfloat162float(hx_)),
                                 __float2bfloat16(v.y - __bfloat162float(hy_)));
    lo[tid*2+1] = __nv_bfloat162(__float2bfloat16(v.z - __bfloat162float(hz_)),
                                 __float2bfloat16(v.w - __bfloat162float(hw_)));
}

// =====================================================================
// convert_wa: w_*_a fp32 [4096,128] -> bf16 hi|lo [4096,256]. grid (512,2)x256
// =====================================================================
__global__ __launch_bounds__(256) void convert_wa_kernel(
    const float* __restrict__ wi, const float* __restrict__ wh)
{
    const int path = blockIdx.y;
    const int idx  = blockIdx.x * 256 + threadIdx.x;   // float4 index
    const float* w = path ? wh : wi;
    float4 v = reinterpret_cast<const float4*>(w)[idx];
    int n = idx >> 5;            // row (128 cols = 32 float4)
    int f = (idx & 31) * 4;
    __nv_bfloat16 hx_ = __float2bfloat16(v.x);
    __nv_bfloat16 hy_ = __float2bfloat16(v.y);
    __nv_bfloat16 hz_ = __float2bfloat16(v.z);
    __nv_bfloat16 hw_ = __float2bfloat16(v.w);
    __nv_bfloat162* dhi = reinterpret_cast<__nv_bfloat162*>(
        g_w2[path] + (size_t)n * K2_ + f);
    __nv_bfloat162* dlo = reinterpret_cast<__nv_bfloat162*>(
        g_w2[path] + (size_t)n * K2_ + 128 + f);
    dhi[0] = __nv_bfloat162(hx_, hy_);
    dhi[1] = __nv_bfloat162(hz_, hw_);
    dlo[0] = __nv_bfloat162(__float2bfloat16(v.x - __bfloat162float(hx_)),
                            __float2bfloat16(v.y - __bfloat162float(hy_)));
    dlo[1] = __nv_bfloat162(__float2bfloat16(v.z - __bfloat162float(hz_)),
                            __float2bfloat16(v.w - __bfloat162float(hw_)));
}

// =====================================================================
// Stage 1 (mma): C[b,f] = (sum_k x[b,k]*wc[f,k]) * scale(b,f), 3-term comp.
// Tile M=64 x N=128, K chunks of 128 (x8), cp.async double buffer.
// smem per buf: A 64x264, W 128x264 bf16. grid (B_/64, 2), 256 thr (8 warps 2x4).
// =====================================================================
#define S1_LD   264
#define S1_ABUF (64 * S1_LD)
#define S1_WBUF (128 * S1_LD)
#define S1_TOT  ((2 * S1_ABUF + 2 * S1_WBUF) * 2)   // 202752 bytes

__device__ __forceinline__ void s1_load_chunk(
    int j, uint32_t aBase, uint32_t wBase,
    const __nv_bfloat16* __restrict__ Ahi, const __nv_bfloat16* __restrict__ Alo,
    const __nv_bfloat16* __restrict__ Whi, const __nv_bfloat16* __restrict__ Wlo,
    int row0, int tid)
{
    #pragma unroll
    for (int it = 0; it < 8; it++) {               // A: 64 rows x 32 chunks
        int idx = tid + it * 256;
        int r = idx >> 5, c = idx & 31;
        int half = c >> 4, cc = c & 15;
        const __nv_bfloat16* src =
            (half ? Alo : Ahi) + (size_t)(row0 + r) * IN_ + j * 128 + cc * 8;
        cp16(aBase + (uint32_t)(r * S1_LD + c * 8) * 2, src);
    }
    #pragma unroll
    for (int it = 0; it < 16; it++) {              // W: 128 rows x 32 chunks
        int idx = tid + it * 256;
        int r = idx >> 5, c = idx & 31;
        int half = c >> 4, cc = c & 15;
        const __nv_bfloat16* src =
            (half ? Wlo : Whi) + (size_t)r * IN_ + j * 128 + cc * 8;
        cp16(wBase + (uint32_t)(r * S1_LD + c * 8) * 2, src);
    }
}

__global__ __launch_bounds__(256) void stage1_mma_kernel(
    const float* __restrict__ topic,
    const float* __restrict__ thw_i, const float* __restrict__ thb_i,
    const float* __restrict__ wb_i,
    const float* __restrict__ thw_h, const float* __restrict__ thb_h,
    const float* __restrict__ wb_h)
{
    extern __shared__ __nv_bfloat16 sm1[];
    __shared__ float sTheta[64][4];

    const int tid  = threadIdx.x;
    const int lane = tid & 31;
    const int wid  = tid >> 5;
    const int path = blockIdx.y;
    const int row0 = blockIdx.x * 64;

    const __nv_bfloat16* __restrict__ Ahi = g_x2[path][0];
    const __nv_bfloat16* __restrict__ Alo = g_x2[path][1];
    const __nv_bfloat16* __restrict__ Whi = g_wc2[path][0];
    const __nv_bfloat16* __restrict__ Wlo = g_wc2[path][1];
    const float* __restrict__ thw = path ? thw_h : thw_i;
    const float* __restrict__ thb = path ? thb_h : thb_i;
    const float* __restrict__ wb  = path ? wb_h  : wb_i;
    __nv_bfloat16* __restrict__ outp = g_a2[path];

    if (tid < 192) {
        int r = tid / 3, t = tid - r * 3;
        const float* tp = topic + (size_t)(row0 + r) * T_;
        sTheta[r][t] = thb[t] + tp[0]*thw[t*T_+0] + tp[1]*thw[t*T_+1] + tp[2]*thw[t*T_+2];
    }

    uint32_t aB[2] = { smem_u32(sm1), smem_u32(sm1 + S1_ABUF) };
    uint32_t wB[2] = { smem_u32(sm1 + 2 * S1_ABUF),
                       smem_u32(sm1 + 2 * S1_ABUF + S1_WBUF) };

    s1_load_chunk(0, aB[0], wB[0], Ahi, Alo, Whi, Wlo, row0, tid);
    CP_COMMIT();

    const int wm = (wid & 1) * 32;
    const int wn = (wid >> 1) * 32;
    const int lr  = lane & 7;
    const int seg = lane >> 3;
    const int l16 = lane & 15;

    float acc[2][4][4];
    #pragma unroll
    for (int mt = 0; mt < 2; mt++)
        #pragma unroll
        for (int nt = 0; nt < 4; nt++)
            #pragma unroll
            for (int j = 0; j < 4; j++) acc[mt][nt][j] = 0.f;

    for (int j = 0; j < 8; j++) {
        const int bf = j & 1;
        if (j < 7) {
            s1_load_chunk(j + 1, aB[(j+1)&1], wB[(j+1)&1],
                          Ahi, Alo, Whi, Wlo, row0, tid);
            CP_COMMIT();
            CP_WAIT(1);
        } else {
            CP_WAIT(0);
        }
        __syncthreads();

        #pragma unroll
        for (int t = 0; t < 3; t++) {
            #pragma unroll
            for (int s = 0; s < 8; s++) {
                const int acol = ((t == 1) ? 128 : 0) + s * 16 + ((seg >> 1) << 3);
                const int bcol = ((t == 2) ? 128 : 0) + s * 16 + ((l16 >> 3) << 3);

                uint32_t a[2][4];
                #pragma unroll
                for (int mt = 0; mt < 2; mt++) {
                    int arow = wm + mt * 16 + lr + ((seg & 1) << 3);
                    uint32_t addr = aB[bf] + (uint32_t)(arow * S1_LD + acol) * 2;
                    asm volatile("ldmatrix.sync.aligned.m8n8.x4.shared.b16 {%0,%1,%2,%3}, [%4];"
                                 : "=r"(a[mt][0]), "=r"(a[mt][1]),
                                   "=r"(a[mt][2]), "=r"(a[mt][3])
                                 : "r"(addr));
                }
                uint32_t b[4][2];
                #pragma unroll
                for (int nt = 0; nt < 4; nt++) {
                    int brow = wn + nt * 8 + (l16 & 7);
                    uint32_t addr = wB[bf] + (uint32_t)(brow * S1_LD + bcol) * 2;
                    asm volatile("ldmatrix.sync.aligned.m8n8.x2.shared.b16 {%0,%1}, [%2];"
                                 : "=r"(b[nt][0]), "=r"(b[nt][1])
                                 : "r"(addr));
                }
                #pragma unroll
                for (int mt = 0; mt < 2; mt++)
                    #pragma unroll
                    for (int nt = 0; nt < 4; nt++) {
                        asm volatile(
                            "mma.sync.aligned.m16n8k16.row.col.f32.bf16.bf16.f32 "
                            "{%0,%1,%2,%3}, {%4,%5,%6,%7}, {%8,%9}, {%0,%1,%2,%3};"
                            : "+f"(acc[mt][nt][0]), "+f"(acc[mt][nt][1]),
                              "+f"(acc[mt][nt][2]), "+f"(acc[mt][nt][3])
                            : "r"(a[mt][0]), "r"(a[mt][1]), "r"(a[mt][2]), "r"(a[mt][3]),
                              "r"(b[nt][0]), "r"(b[nt][1]));
                    }
            }
        }
        __syncthreads();
    }

    // ---- epilogue: scale by theta·wb, split hi|lo, write bf162 pairs ----
    const int em = lane >> 2;
    const int en = (lane & 3) * 2;
    #pragma unroll
    for (int nt = 0; nt < 4; nt++) {
        const int n = wn + nt * 8 + en;
        float w0a = wb[n*T_+0],     w1a = wb[n*T_+1],     w2a = wb[n*T_+2];
        float w0b = wb[(n+1)*T_+0], w1b = wb[(n+1)*T_+1], w2b = wb[(n+1)*T_+2];
        #pragma unroll
        for (int mt = 0; mt < 2; mt++) {
            #pragma unroll
            for (int half = 0; half < 2; half++) {
                int m = wm + mt * 16 + em + half * 8;
                float th0 = sTheta[m][0], th1 = sTheta[m][1], th2 = sTheta[m][2];
                float sc0 = th0*w0a + th1*w1a + th2*w2a;
                float sc1 = th0*w0b + th1*w1b + th2*w2b;
                float v0 = acc[mt][nt][half*2 + 0] * sc0;
                float v1 = acc[mt][nt][half*2 + 1] * sc1;
                __nv_bfloat16 h0 = __float2bfloat16(v0);
                __nv_bfloat16 h1 = __float2bfloat16(v1);
                size_t base = (size_t)(row0 + m) * K2_ + n;
                *reinterpret_cast<__nv_bfloat162*>(&outp[base]) =
                    __nv_bfloat162(h0, h1);
                *reinterpret_cast<__nv_bfloat162*>(&outp[base + 128]) =
                    __nv_bfloat162(__float2bfloat16(v0 - __bfloat162float(h0)),
                                   __float2bfloat16(v1 - __bfloat162float(h1)));
            }
        }
    }
}

// =====================================================================
// Stage 2: bf16 mma.sync GEMM, 3-term via column maps (no smem replication).
// smem holds stored K=256 per operand. CTA 128x128, 8 warps (2x4) 64x32.
// grid = (G/128, B/128, 2), 256 threads.
// =====================================================================
#define S2_LD   264
#define S2_TOT  (2 * 128 * S2_LD * 2)               // 135168 bytes

__global__ __launch_bounds__(256) void stage2_mma_kernel()
{
    extern __shared__ __nv_bfloat16 sm2[];
    __nv_bfloat16* As = sm2;                  // [128][264]
    __nv_bfloat16* Bs = sm2 + 128 * S2_LD;    // [128][264]

    const int tid  = threadIdx.x;
    const int lane = tid & 31;
    const int wid  = tid >> 5;
    const int path = blockIdx.z;
    const int row0 = blockIdx.y * 128;
    const int col0 = blockIdx.x * 128;

    const __nv_bfloat16* __restrict__ A = g_a2[path];
    const __nv_bfloat16* __restrict__ W = g_w2[path];
    float* __restrict__ O = path ? g_hg : g_ig;

    const uint32_t as_base = smem_u32(As);
    const uint32_t bs_base = smem_u32(Bs);

    #pragma unroll
    for (int it = 0; it < 16; it++) {
        int idx = tid + it * 256;
        int r = idx >> 5, c = idx & 31;
        cp16(as_base + (uint32_t)(r * S2_LD + c * 8) * 2,
             A + (size_t)(row0 + r) * K2_ + c * 8);
    }
    #pragma unroll
    for (int it = 0; it < 16; it++) {
        int idx = tid + it * 256;
        int r = idx >> 5, c = idx & 31;
        cp16(bs_base + (uint32_t)(r * S2_LD + c * 8) * 2,
             W + (size_t)(col0 + r) * K2_ + c * 8);
    }
    CP_COMMIT();
    CP_WAIT(0);
    __syncthreads();

    const int wm = (wid & 1) * 64;
    const int wn = (wid >> 1) * 32;
    const int lr  = lane & 7;
    const int seg = lane >> 3;
    const int l16 = lane & 15;

    float acc[4][4][4];
    #pragma unroll
    for (int mt = 0; mt < 4; mt++)
        #pragma unroll
        for (int nt = 0; nt < 4; nt++)
            #pragma unroll
            for (int j = 0; j < 4; j++) acc[mt][nt][j] = 0.f;

    #pragma unroll
    for (int t = 0; t < 3; t++) {
        #pragma unroll
        for (int s = 0; s < 8; s++) {
            const int acol = ((t == 1) ? 128 : 0) + s * 16 + ((seg >> 1) << 3);
            const int bcol = ((t == 2) ? 128 : 0) + s * 16 + ((l16 >> 3) << 3);

            uint32_t a[4][4];
            #pragma unroll
            for (int mt = 0; mt < 4; mt++) {
                int arow = wm + mt * 16 + lr + ((seg & 1) << 3);
                uint32_t addr = as_base + (uint32_t)(arow * S2_LD + acol) * 2;
                asm volatile("ldmatrix.sync.aligned.m8n8.x4.shared.b16 {%0,%1,%2,%3}, [%4];"
                             : "=r"(a[mt][0]), "=r"(a[mt][1]),
                               "=r"(a[mt][2]), "=r"(a[mt][3])
                             : "r"(addr));
            }
            uint32_t b[4][2];
            #pragma unroll
            for (int nt = 0; nt < 4; nt++) {
                int brow = wn + nt * 8 + (l16 & 7);
                uint32_t addr = bs_base + (uint32_t)(brow * S2_LD + bcol) * 2;
                asm volatile("ldmatrix.sync.aligned.m8n8.x2.shared.b16 {%0,%1}, [%2];"
                             : "=r"(b[nt][0]), "=r"(b[nt][1])
                             : "r"(addr));
            }
            #pragma unroll
            for (int mt = 0; mt < 4; mt++)
                #pragma unroll
                for (int nt = 0; nt < 4; nt++) {
                    asm volatile(
                        "mma.sync.aligned.m16n8k16.row.col.f32.bf16.bf16.f32 "
                        "{%0,%1,%2,%3}, {%4,%5,%6,%7}, {%8,%9}, {%0,%1,%2,%3};"
                        : "+f"(acc[mt][nt][0]), "+f"(acc[mt][nt][1]),
                          "+f"(acc[mt][nt][2]), "+f"(acc[mt][nt][3])
                        : "r"(a[mt][0]), "r"(a[mt][1]), "r"(a[mt][2]), "r"(a[mt][3]),
                          "r"(b[nt][0]), "r"(b[nt][1]));
                }
        }
    }

    // ---- epilogue ----
    const int em = lane >> 2;
    const int en = (lane & 3) * 2;
    #pragma unroll
    for (int mt = 0; mt < 4; mt++) {
        #pragma unroll
        for (int nt = 0; nt < 4; nt++) {
            int m = row0 + wm + mt * 16 + em;
            int n = col0 + wn + nt * 8 + en;
            *reinterpret_cast<float2*>(&O[(size_t)m * G_ + n]) =
                make_float2(acc[mt][nt][0], acc[mt][nt][1]);
            *reinterpret_cast<float2*>(&O[(size_t)(m + 8) * G_ + n]) =
                make_float2(acc[mt][nt][2], acc[mt][nt][3]);
        }
    }
}

// =====================================================================
// Stage 3: per-row LN(igates)+LN(hgates), gates, cell update, LN(cell).
// Fully float4-vectorized. One CTA (256 thr) per batch row.
// =====================================================================
__device__ __forceinline__ float sigm(float x) { return 1.f / (1.f + expf(-x)); }

__device__ __forceinline__ float2 block_reduce2(float s, float q, float* red)
{
    __syncthreads();
    #pragma unroll
    for (int o = 16; o > 0; o >>= 1) {
        s += __shfl_xor_sync(0xffffffffu, s, o);
        q += __shfl_xor_sync(0xffffffffu, q, o);
    }
    int w = threadIdx.x >> 5, l = threadIdx.x & 31;
    if (l == 0) { red[w] = s; red[8 + w] = q; }
    __syncthreads();
    if (w == 0) {
        s = (l < 8) ? red[l] : 0.f;
        q = (l < 8) ? red[8 + l] : 0.f;
        #pragma unroll
        for (int o = 4; o > 0; o >>= 1) {
            s += __shfl_xor_sync(0xffffffffu, s, o);
            q += __shfl_xor_sync(0xffffffffu, q, o);
        }
        if (l == 0) { red[0] = s; red[1] = q; }
    }
    __syncthreads();
    return make_float2(red[0], red[1]);
}

__global__ __launch_bounds__(256) void stage3_kernel(
    const float* __restrict__ cx,
    const float* __restrict__ lniw, const float* __restrict__ lnib,
    const float* __restrict__ lnhw, const float* __restrict__ lnhb,
    const float* __restrict__ lncw, const float* __restrict__ lncb,
    float* __restrict__ out)
{
    __shared__ float4 s_ig[1024];
    __shared__ float4 s_hg[1024];
    __shared__ float red[16];

    const int r   = blockIdx.x;
    const int tid = threadIdx.x;
    const float4* __restrict__ ig4 = reinterpret_cast<const float4*>(g_ig + (size_t)r * G_);
    const float4* __restrict__ hg4 = reinterpret_cast<const float4*>(g_hg + (size_t)r * G_);

    float s = 0.f, q = 0.f;
    #pragma unroll
    for (int i = 0; i < 4; i++) {
        int n = tid + i * 256;
        float4 v = ig4[n];
        s_ig[n] = v;
        s += v.x + v.y + v.z + v.w;
        q += v.x*v.x + v.y*v.y + v.z*v.z + v.w*v.w;
    }
    float2 ri = block_reduce2(s, q, red);
    float mu_i = ri.x * (1.f / G_);
    float rstd_i = rsqrtf(ri.y * (1.f / G_) - mu_i * mu_i + LN_EPS);

    s = 0.f; q = 0.f;
    #pragma unroll
    for (int i = 0; i < 4; i++) {
        int n = tid + i * 256;
        float4 v = hg4[n];
        s_hg[n] = v;
        s += v.x + v.y + v.z + v.w;
        q += v.x*v.x + v.y*v.y + v.z*v.z + v.w*v.w;
    }
    float2 rh = block_reduce2(s, q, red);
    float mu_h = rh.x * (1.f / G_);
    float rstd_h = rsqrtf(rh.y * (1.f / G_) - mu_h * mu_h + LN_EPS);

    // each thread owns 4 consecutive hidden units (float4 index = tid)
    const float4* lniw4 = reinterpret_cast<const float4*>(lniw);
    const float4* lnib4 = reinterpret_cast<const float4*>(lnib);
    const float4* lnhw4 = reinterpret_cast<const float4*>(lnhw);
    const float4* lnhb4 = reinterpret_cast<const float4*>(lnhb);

    float4 gi_v[4], gh_v[4], wi_v[4], bi_v[4], wh_v[4], bh_v[4];
    #pragma unroll
    for (int g = 0; g < 4; g++) {
        int n = tid + g * 256;
        gi_v[g] = s_ig[n];  gh_v[g] = s_hg[n];
        wi_v[g] = lniw4[n]; bi_v[g] = lnib4[n];
        wh_v[g] = lnhw4[n]; bh_v[g] = lnhb4[n];
    }
    float4 cxv = reinterpret_cast<const float4*>(cx + (size_t)r * H_)[tid];

    float cc[4], oo[4];
    float cs = 0.f, cq = 0.f;
    #pragma unroll
    for (int c = 0; c < 4; c++) {
        #define GVAL(g) ((f4c(gi_v[g],c) - mu_i) * rstd_i * f4c(wi_v[g],c) + f4c(bi_v[g],c) + \
                         (f4c(gh_v[g],c) - mu_h) * rstd_h * f4c(wh_v[g],c) + f4c(bh_v[g],c))
        float gi = sigm(GVAL(0));
        float gf = sigm(GVAL(1));
        float gg = tanhf(GVAL(2));
        float go = sigm(GVAL(3));
        #undef GVAL
        float c_ = gf * f4c(cxv, c) + gi * gg;
        cc[c] = c_; oo[c] = go;
        cs += c_; cq += c_ * c_;
    }
    float2 rc = block_reduce2(cs, cq, red);
    float mu_c = rc.x * (1.f / H_);
    float rstd_c = rsqrtf(rc.y * (1.f / H_) - mu_c * mu_c + LN_EPS);

    float4 wcv = reinterpret_cast<const float4*>(lncw)[tid];
    float4 bcv = reinterpret_cast<const float4*>(lncb)[tid];
    float4 hyv, cyv;
    #pragma unroll
    for (int c = 0; c < 4; c++) {
        float cy = (cc[c] - mu_c) * rstd_c * f4c(wcv, c) + f4c(bcv, c);
        reinterpret_cast<float*>(&cyv)[c] = cy;
        reinterpret_cast<float*>(&hyv)[c] = oo[c] * tanhf(cy);
    }
    float4* out4 = reinterpret_cast<float4*>(out);
    out4[(size_t)r * 256 + tid] = hyv;
    out4[(size_t)B_ * 256 + (size_t)r * 256 + tid] = cyv;
}

// =====================================================================
extern "C" void kernel_launch(void* const* d_in, const int* in_sizes, int n_in,
                              void* d_out, int out_size)
{
    const float* input_ = (const float*)d_in[0];
    const float* hx     = (const float*)d_in[1];
    const float* cx     = (const float*)d_in[2];
    const float* topic  = (const float*)d_in[3];
    const float* w_ih_a = (const float*)d_in[4];
    const float* w_ih_b = (const float*)d_in[5];
    const float* w_ih_c = (const float*)d_in[6];
    const float* w_hh_a = (const float*)d_in[7];
    const float* w_hh_b = (const float*)d_in[8];
    const float* w_hh_c = (const float*)d_in[9];
    const float* th_ih_w = (const float*)d_in[10];
    const float* th_ih_b = (const float*)d_in[11];
    const float* th_hh_w = (const float*)d_in[12];
    const float* th_hh_b = (const float*)d_in[13];
    const float* ln_i_w  = (const float*)d_in[14];
    const float* ln_i_b  = (const float*)d_in[15];
    const float* ln_h_w  = (const float*)d_in[16];
    const float* ln_h_b  = (const float*)d_in[17];
    const float* ln_c_w  = (const float*)d_in[18];
    const float* ln_c_b  = (const float*)d_in[19];

    cudaFuncSetAttribute(stage1_mma_kernel,
                         cudaFuncAttributeMaxDynamicSharedMemorySize, S1_TOT);
    cudaFuncSetAttribute(stage2_mma_kernel,
                         cudaFuncAttributeMaxDynamicSharedMemorySize, S2_TOT);

    convert_x_kernel<<<dim3(B_, 2), 256>>>(input_, hx);
    convert_wc_kernel<<<dim3(F_, 2), 256>>>(w_ih_c, w_hh_c);
    convert_wa_kernel<<<dim3(512, 2), 256>>>(w_ih_a, w_hh_a);

    stage1_mma_kernel<<<dim3(B_ / 64, 2), 256, S1_TOT>>>(
        topic, th_ih_w, th_ih_b, w_ih_b, th_hh_w, th_hh_b, w_hh_b);

    stage2_mma_kernel<<<dim3(G_ / 128, B_ / 128, 2), 256, S2_TOT>>>();

    stage3_kernel<<<B_, 256>>>(cx, ln_i_w, ln_i_b, ln_h_w, ln_h_b,
                               ln_c_w, ln_c_b, (float*)d_out);
}